// round 7
// baseline (speedup 1.0000x reference)
#include <cuda_runtime.h>
#include <math.h>

#define COL 14
#define NJ 14
#define NPIX 196
#define NB 8192
#define NJOINT (NB * NJ)                   // 114688
#define THREADS 256
#define NWARPS 8
#define JPW 4
#define NBLOCKS (NJOINT / (NWARPS * JPW))  // 3584 exactly

struct GParams {
    float GT[NPIX];     // GT[c*14+r] = G[r][c]  (row c of G^T)
    float cmin[COL];
    float cmax[COL];
    float T2[NPIX];     // T2[yic*14+xic] = sum over pixels of ttn^2
};

__device__ float    g_d1[NBLOCKS];
__device__ float    g_d2[NBLOCKS];
__device__ float    g_cnt[NBLOCKS];
__device__ unsigned g_ticket;   // zero-init at load; net-zero per run (last block resets)

// ---- packed f32x2 helpers (Blackwell) ----
__device__ __forceinline__ unsigned long long pack2(float lo, float hi) {
    unsigned long long r;
    asm("mov.b64 %0,{%1,%2};" : "=l"(r) : "f"(lo), "f"(hi));
    return r;
}
__device__ __forceinline__ void unpack2(unsigned long long p, float& lo, float& hi) {
    asm("mov.b64 {%0,%1},%2;" : "=f"(lo), "=f"(hi) : "l"(p));
}
__device__ __forceinline__ unsigned long long mul2(unsigned long long a, unsigned long long b) {
    unsigned long long r;
    asm("mul.rn.f32x2 %0,%1,%2;" : "=l"(r) : "l"(a), "l"(b));
    return r;
}
__device__ __forceinline__ unsigned long long add2(unsigned long long a, unsigned long long b) {
    unsigned long long r;
    asm("add.rn.f32x2 %0,%1,%2;" : "=l"(r) : "l"(a), "l"(b));
    return r;
}
__device__ __forceinline__ unsigned long long fma2(unsigned long long a, unsigned long long b,
                                                   unsigned long long c) {
    unsigned long long r;
    asm("fma.rn.f32x2 %0,%1,%2,%3;" : "=l"(r) : "l"(a), "l"(b), "l"(c));
    return r;
}

__global__ __launch_bounds__(THREADS) void main_kernel(
    const float* __restrict__ outp,
    const float* __restrict__ t,
    const float* __restrict__ v,
    float* __restrict__ o,
    const GParams gp)
{
    __shared__ __align__(16) float sGT[NPIX];
    __shared__ float scmin[COL], scmax[COL];
    __shared__ float sred[NWARPS][3];
    __shared__ int   sBidx[NWARPS][JPW];
    __shared__ int   s_last;
    __shared__ double dra[NWARPS], drb[NWARPS], drc[NWARPS];

    const int tid = threadIdx.x;
    if (tid < NPIX) sGT[tid] = gp.GT[tid];
    if (tid < COL) { scmin[tid] = gp.cmin[tid]; scmax[tid] = gp.cmax[tid]; }
    __syncthreads();

    const int lane = tid & 31;
    const int warp = tid >> 5;
    const int gw = blockIdx.x * NWARPS + warp;
    const int joint0 = gw * JPW;
    const bool hasB = lane < 17;
    const int base4 = 4 * lane;

    // ---- per-lane pair geometry: 4 pairs, each pair lies in one template row ----
    // pair starts: e0 = {4l, 4l+2, 128+4l, 128+4l+2}; rows start at even e, so
    // y is constant within a pair and x0 is even (LDS.64-aligned gx pair).
    int ybO[4], xbO[4];
    {
        #pragma unroll
        for (int p = 0; p < 4; ++p) {
            int e0 = (p < 2) ? (base4 + 2 * p) : (128 + base4 + 2 * (p - 2));
            if (p >= 2 && !hasB) e0 = 0;     // clamp (h is zero there anyway)
            int y = e0 / COL;
            ybO[p] = y * 4;
            xbO[p] = (e0 - y * COL) * 4;
        }
    }

    // ---- t/v for 4 joints (uniform broadcast) ----
    const float4 tA = *reinterpret_cast<const float4*>(t + 8 * (size_t)gw);
    const float4 tB = *reinterpret_cast<const float4*>(t + 8 * (size_t)gw + 4);
    const float4 vA = *reinterpret_cast<const float4*>(v + 8 * (size_t)gw);
    const float4 vB = *reinterpret_cast<const float4*>(v + 8 * (size_t)gw + 4);
    const float t0k[4] = {tA.x, tA.z, tB.x, tB.z};
    const float t1k[4] = {tA.y, tA.w, tB.y, tB.w};
    const float v0k[4] = {vA.x, vA.z, vB.x, vB.z};

    // ---- front-batched heatmap loads: 8 LDG.128 in flight ----
    float4 H0[JPW], H1[JPW];
    {
        int bb = joint0 / NJ;
        int jj = joint0 - bb * NJ;
        #pragma unroll
        for (int k = 0; k < JPW; ++k) {
            const float* hb = outp + ((size_t)bb * (3 * NJ) + jj) * NPIX;
            H0[k] = __ldcs(reinterpret_cast<const float4*>(hb + base4));
            H1[k] = make_float4(0.0f, 0.0f, 0.0f, 0.0f);
            if (hasB) H1[k] = __ldcs(reinterpret_cast<const float4*>(hb + 128 + base4));
            ++jj; if (jj == NJ) { jj = 0; ++bb; }
        }
    }

    float d1 = 0.0f;

    #pragma unroll
    for (int k = 0; k < JPW; ++k) {
        const float4 a = H0[k];
        const float4 b = H1[k];
        const unsigned long long p01 = pack2(a.x, a.y);
        const unsigned long long p23 = pack2(a.z, a.w);
        const unsigned long long p45 = pack2(b.x, b.y);
        const unsigned long long p67 = pack2(b.z, b.w);

        // Sum h^2 over this lane's elements (tail zeros contribute 0)
        unsigned long long s2 = fma2(p01, p01, mul2(p23, p23));
        s2 = fma2(p45, p45, s2);
        s2 = fma2(p67, p67, s2);
        float h2lo, h2hi; unpack2(s2, h2lo, h2hi);
        const float ph2 = h2lo + h2hi;

        const float t0 = t0k[k], t1 = t1k[k], v0 = v0k[k];
        const int xi = (int)(t0 * 14.0f);
        const int yi = (int)(t1 * 14.0f);
        const bool inb = (xi >= 0) && (xi <= COL - 1) && (yi >= 0) && (yi <= COL - 1);
        const bool vis = ((int)v0) == 1;
        const bool scat = vis && inb;         // warp-uniform

        if (scat) {
            // Sum h (for the cross term)
            unsigned long long sh = add2(add2(p01, p23), add2(p45, p67));
            float shlo, shhi; unpack2(sh, shlo, shhi);
            const float ph = shlo + shhi;

            // Sum h*tt : per pair one gy scalar LDS + one gx LDS.64
            const char* gyrowB = reinterpret_cast<const char*>(sGT + yi * COL);
            const char* gxrowB = reinterpret_cast<const char*>(sGT + xi * COL);
            unsigned long long acc = 0ull;
            {
                const float gy = *(const float*)(gyrowB + ybO[0]);
                const unsigned long long gx2 = *(const unsigned long long*)(gxrowB + xbO[0]);
                acc = fma2(mul2(gx2, p01), pack2(gy, gy), acc);
            }
            {
                const float gy = *(const float*)(gyrowB + ybO[1]);
                const unsigned long long gx2 = *(const unsigned long long*)(gxrowB + xbO[1]);
                acc = fma2(mul2(gx2, p23), pack2(gy, gy), acc);
            }
            {
                const float gy = *(const float*)(gyrowB + ybO[2]);
                const unsigned long long gx2 = *(const unsigned long long*)(gxrowB + xbO[2]);
                acc = fma2(mul2(gx2, p45), pack2(gy, gy), acc);
            }
            {
                const float gy = *(const float*)(gyrowB + ybO[3]);
                const unsigned long long gx2 = *(const unsigned long long*)(gxrowB + xbO[3]);
                acc = fma2(mul2(gx2, p67), pack2(gy, gy), acc);
            }
            float htlo, hthi; unpack2(acc, htlo, hthi);
            const float phtt = htlo + hthi;

            const float mn = scmin[yi] * scmin[xi];
            const float mx = scmax[yi] * scmax[xi];
            const float inv = 1.0f / (mx - mn);
            const float nmi = -mn * inv;

            // d1 += ph2 - 2*(inv*phtt + nmi*ph)  [+ T2 once per joint]
            d1 += fmaf(-2.0f * inv, phtt, fmaf(-2.0f * nmi, ph, ph2));
            if (lane == 0) d1 += gp.T2[yi * COL + xi];

            // ---- argmax (visible joints only) ----
            float best = fmaxf(fmaxf(a.x, a.y), fmaxf(a.z, a.w));
            if (hasB) best = fmaxf(best, fmaxf(fmaxf(b.x, b.y), fmaxf(b.z, b.w)));
            int idx = 0x7fffffff;
            if (hasB) {
                idx = (b.w == best) ? (131 + base4) : idx;
                idx = (b.z == best) ? (130 + base4) : idx;
                idx = (b.y == best) ? (129 + base4) : idx;
                idx = (b.x == best) ? (128 + base4) : idx;
            }
            idx = (a.w == best) ? (3 + base4) : idx;
            idx = (a.z == best) ? (2 + base4) : idx;
            idx = (a.y == best) ? (1 + base4) : idx;
            idx = (a.x == best) ? (base4) : idx;

            unsigned u = __float_as_uint(best);
            unsigned mono = ((int)u < 0) ? ~u : (u | 0x80000000u);
            unsigned mmax = __reduce_max_sync(0xffffffffu, mono);
            int cand = (mono == mmax) ? idx : 0x7fffffff;
            int bidx = __reduce_min_sync(0xffffffffu, cand);
            if (lane == 0) sBidx[warp][k] = bidx;
        } else {
            // invisible / off-grid: d1 += sum_{y>=1} h^2 = ph2 - (row-0 part)
            float pr = 0.0f;
            if (lane < 4) {
                pr = fmaf(a.x, a.x, a.y * a.y);          // e = 4l, 4l+1 (row 0)
                if (lane < 3) pr += fmaf(a.z, a.z, a.w * a.w);  // e = 4l+2, 4l+3
            }
            d1 += ph2 - pr;
        }
    }

    // warp-reduce d1
    #pragma unroll
    for (int off = 16; off; off >>= 1)
        d1 += __shfl_xor_sync(0xffffffffu, d1, off);

    __syncwarp();

    // ---- phase B: gathers only for visible joints, lanes 0..3 ----
    float d2 = 0.0f, cntf = 0.0f;
    if (lane < JPW) {
        const int joint = joint0 + lane;
        const float t0 = t0k[lane];
        const float t1 = t1k[lane];
        const float v0 = v0k[lane];
        const int xi = (int)(t0 * 14.0f);
        const int yi = (int)(t1 * 14.0f);
        const bool inb = (xi >= 0) && (xi <= COL - 1) && (yi >= 0) && (yi <= COL - 1);
        const bool vis = ((int)v0) == 1;
        const float vef = (vis && !inb) ? 0.0f : v0;
        const float veI = (((int)vef) == 1) ? 1.0f : 0.0f;
        cntf = veI;

        if (vis && inb) {
            const int b2 = joint / NJ;
            const int j2 = joint - b2 * NJ;
            const int bidx = sBidx[warp][lane];
            const size_t ob = (size_t)b2 * (3 * NJ) * NPIX;
            const float ox = outp[ob + (size_t)(NJ + j2) * NPIX + bidx];
            const float oy = outp[ob + (size_t)(2 * NJ + j2) * NPIX + bidx];
            const int yc = bidx / COL;
            const int xc = bidx - yc * COL;
            const float px = (ox + (float)xc) * (1.0f / 14.0f);
            const float py = (oy + (float)yc) * (1.0f / 14.0f);
            const float dx = (px - t0) * vef;
            const float dy = (py - t1) * vef;
            d2 = fmaf(dx, dx, dy * dy);
        }
    }
    #pragma unroll
    for (int off = 1; off <= 2; off <<= 1) {
        d2   += __shfl_xor_sync(0xffffffffu, d2, off);
        cntf += __shfl_xor_sync(0xffffffffu, cntf, off);
    }

    if (lane == 0) { sred[warp][0] = d1; sred[warp][1] = d2; sred[warp][2] = cntf; }
    __syncthreads();

    if (tid == 0) {
        float a = 0.0f, bsum = 0.0f, c = 0.0f;
        #pragma unroll
        for (int w = 0; w < NWARPS; ++w) { a += sred[w][0]; bsum += sred[w][1]; c += sred[w][2]; }
        g_d1[blockIdx.x] = a;
        g_d2[blockIdx.x] = bsum;
        g_cnt[blockIdx.x] = c;
        __threadfence();
        unsigned old = atomicAdd(&g_ticket, 1u);
        s_last = (old == NBLOCKS - 1);
    }
    __syncthreads();

    // ---- last block: grid reduction ----
    if (s_last) {
        if (tid == 0) g_ticket = 0;          // net-zero per run
        __threadfence();
        double a = 0.0, bsum = 0.0, c = 0.0;
        for (int i = tid; i < NBLOCKS; i += THREADS) {
            a    += (double)g_d1[i];
            bsum += (double)g_d2[i];
            c    += (double)g_cnt[i];
        }
        #pragma unroll
        for (int off = 16; off; off >>= 1) {
            a    += __shfl_xor_sync(0xffffffffu, a, off);
            bsum += __shfl_xor_sync(0xffffffffu, bsum, off);
            c    += __shfl_xor_sync(0xffffffffu, c, off);
        }
        if (lane == 0) { dra[warp] = a; drb[warp] = bsum; drc[warp] = c; }
        __syncthreads();
        if (tid == 0) {
            double A = 0.0, B = 0.0, C = 0.0;
            #pragma unroll
            for (int w = 0; w < NWARPS; ++w) { A += dra[w]; B += drb[w]; C += drc[w]; }
            o[0] = (float)(A / C + B / C);   // n2 == cnt (v is a tiled 0/1 mask)
        }
    }
}

extern "C" void kernel_launch(void* const* d_in, const int* in_sizes, int n_in,
                              void* d_out, int out_size)
{
    const float* outp = (const float*)d_in[0];
    const float* t    = (const float*)d_in[1];
    const float* v    = (const float*)d_in[2];

    // Host-side Gaussian matrix + T2 table, matching the numpy reference.
    GParams gp;
    {
        double w[9], ws = 0.0;
        for (int k = 0; k < 9; ++k) { w[k] = exp(-0.5 * (double)((k - 4) * (k - 4))); ws += w[k]; }
        for (int k = 0; k < 9; ++k) w[k] /= ws;
        for (int r = 0; r < COL; ++r)
            for (int c = 0; c < COL; ++c) {
                double s = 0.0;
                for (int k = 0; k < 9; ++k) {
                    int rr = r + k;   // padded row, pad=4, 'symmetric'
                    int m = (rr < 4) ? (3 - rr) : ((rr > 17) ? (31 - rr) : (rr - 4));
                    if (m == c) s += w[k];
                }
                gp.GT[c * COL + r] = (float)s;
            }
        for (int c = 0; c < COL; ++c) {
            float mn = 1e30f, mx = -1e30f;
            for (int r = 0; r < COL; ++r) {
                float gv = gp.GT[c * COL + r];
                mn = fminf(mn, gv);
                mx = fmaxf(mx, gv);
            }
            gp.cmin[c] = mn;
            gp.cmax[c] = mx;
        }
        // T2[yic][xic] = sum over (y,x) of ((gy[y]*gx[x]-mn)/(mx-mn))^2
        for (int yic = 0; yic < COL; ++yic)
            for (int xic = 0; xic < COL; ++xic) {
                float mn = gp.cmin[yic] * gp.cmin[xic];
                float mx = gp.cmax[yic] * gp.cmax[xic];
                float inv = 1.0f / (mx - mn);
                double s = 0.0;
                for (int y = 0; y < COL; ++y)
                    for (int x = 0; x < COL; ++x) {
                        float tt = gp.GT[yic * COL + y] * gp.GT[xic * COL + x];
                        float ttn = (tt - mn) * inv;
                        s += (double)ttn * (double)ttn;
                    }
                gp.T2[yic * COL + xic] = (float)s;
            }
    }

    main_kernel<<<NBLOCKS, THREADS>>>(outp, t, v, (float*)d_out, gp);
}

// round 8
// speedup vs baseline: 1.0907x; 1.0907x over previous
#include <cuda_runtime.h>
#include <math.h>

#define COL 14
#define NJ 14
#define NPIX 196
#define NB 8192
#define NJOINT (NB * NJ)                   // 114688
#define THREADS 256
#define NWARPS 8
#define JPW 4
#define NBLOCKS (NJOINT / (NWARPS * JPW))  // 3584 exactly

struct GParams {
    float GT[NPIX];     // GT[c*14+r] = G[r][c]  (row c of G^T)
    float cmin[COL];
    float cmax[COL];
    float T2[NPIX];     // T2[yic*14+xic] = sum over pixels of ttn^2
};

__device__ float    g_d1[NBLOCKS];
__device__ float    g_d2[NBLOCKS];
__device__ float    g_cnt[NBLOCKS];
__device__ unsigned g_ticket;   // zero-init at load; net-zero per run (last block resets)

// ---- packed f32x2 helpers (Blackwell) ----
__device__ __forceinline__ unsigned long long pack2(float lo, float hi) {
    unsigned long long r;
    asm("mov.b64 %0,{%1,%2};" : "=l"(r) : "f"(lo), "f"(hi));
    return r;
}
__device__ __forceinline__ void unpack2(unsigned long long p, float& lo, float& hi) {
    asm("mov.b64 {%0,%1},%2;" : "=f"(lo), "=f"(hi) : "l"(p));
}
__device__ __forceinline__ unsigned long long mul2(unsigned long long a, unsigned long long b) {
    unsigned long long r;
    asm("mul.rn.f32x2 %0,%1,%2;" : "=l"(r) : "l"(a), "l"(b));
    return r;
}
__device__ __forceinline__ unsigned long long add2(unsigned long long a, unsigned long long b) {
    unsigned long long r;
    asm("add.rn.f32x2 %0,%1,%2;" : "=l"(r) : "l"(a), "l"(b));
    return r;
}
__device__ __forceinline__ unsigned long long fma2(unsigned long long a, unsigned long long b,
                                                   unsigned long long c) {
    unsigned long long r;
    asm("fma.rn.f32x2 %0,%1,%2,%3;" : "=l"(r) : "l"(a), "l"(b), "l"(c));
    return r;
}

#define CP_ASYNC16(dst_u32, src_ptr) \
    asm volatile("cp.async.cg.shared.global [%0], [%1], 16;" \
                 :: "r"(dst_u32), "l"(src_ptr) : "memory")
#define CP_COMMIT() asm volatile("cp.async.commit_group;" ::: "memory")
#define CP_WAIT0()  asm volatile("cp.async.wait_group 0;" ::: "memory")

__global__ __launch_bounds__(THREADS) void main_kernel(
    const float* __restrict__ outp,
    const float* __restrict__ t,
    const float* __restrict__ v,
    float* __restrict__ o,
    const GParams gp)
{
    __shared__ __align__(16) float sH[NWARPS * JPW * NPIX];   // 25088 B
    __shared__ __align__(16) float sGT[NPIX];
    __shared__ float scmin[COL], scmax[COL];
    __shared__ float sred[NWARPS][3];
    __shared__ int   sBidx[NWARPS][JPW];
    __shared__ int   s_last;
    __shared__ double dra[NWARPS], drb[NWARPS], drc[NWARPS];

    const int tid = threadIdx.x;
    if (tid < NPIX) sGT[tid] = gp.GT[tid];
    if (tid < COL) { scmin[tid] = gp.cmin[tid]; scmax[tid] = gp.cmax[tid]; }
    __syncthreads();

    const int lane = tid & 31;
    const int warp = tid >> 5;
    const int gw = blockIdx.x * NWARPS + warp;
    const int joint0 = gw * JPW;
    const bool hasB = lane < 17;
    const int base4 = 4 * lane;
    const int baseByte = 16 * lane;

    // ---- cp.async front-batch: all 4 joints' heatmaps into per-warp smem ----
    const unsigned sHbase =
        (unsigned)__cvta_generic_to_shared(&sH[warp * (JPW * NPIX)]);
    {
        int bb = joint0 / NJ;
        int jj = joint0 - bb * NJ;
        #pragma unroll
        for (int k = 0; k < JPW; ++k) {
            const char* hb = reinterpret_cast<const char*>(
                outp + ((size_t)bb * (3 * NJ) + jj) * NPIX);
            const unsigned dst = sHbase + k * (NPIX * 4);
            CP_ASYNC16(dst + baseByte, hb + baseByte);            // floats 0..127
            if (hasB)
                CP_ASYNC16(dst + 512 + baseByte, hb + 512 + baseByte); // 128..195
            ++jj; if (jj == NJ) { jj = 0; ++bb; }
        }
        CP_COMMIT();
    }

    // ---- per-lane pair geometry: pair rows constant, x0 even (LDS.64 ok) ----
    int ybO[4], xbO[4];
    {
        #pragma unroll
        for (int p = 0; p < 4; ++p) {
            int e0 = (p < 2) ? (base4 + 2 * p) : (128 + base4 + 2 * (p - 2));
            if (p >= 2 && !hasB) e0 = 0;
            int y = e0 / COL;
            ybO[p] = y * 4;
            xbO[p] = (e0 - y * COL) * 4;
        }
    }

    // ---- t/v for 4 joints (uniform broadcast) ----
    const float4 tA = *reinterpret_cast<const float4*>(t + 8 * (size_t)gw);
    const float4 tB = *reinterpret_cast<const float4*>(t + 8 * (size_t)gw + 4);
    const float4 vA = *reinterpret_cast<const float4*>(v + 8 * (size_t)gw);
    const float4 vB = *reinterpret_cast<const float4*>(v + 8 * (size_t)gw + 4);
    const float t0k[4] = {tA.x, tA.z, tB.x, tB.z};
    const float t1k[4] = {tA.y, tA.w, tB.y, tB.w};
    const float v0k[4] = {vA.x, vA.z, vB.x, vB.z};

    CP_WAIT0();   // each lane reads only bytes it loaded itself -> no syncwarp needed

    float d1 = 0.0f;
    const float* sHw = &sH[warp * (JPW * NPIX)];

    #pragma unroll
    for (int k = 0; k < JPW; ++k) {
        const float4 a = *reinterpret_cast<const float4*>(sHw + k * NPIX + base4);
        float4 b = make_float4(0.0f, 0.0f, 0.0f, 0.0f);
        if (hasB) b = *reinterpret_cast<const float4*>(sHw + k * NPIX + 128 + base4);

        const unsigned long long p01 = pack2(a.x, a.y);
        const unsigned long long p23 = pack2(a.z, a.w);
        const unsigned long long p45 = pack2(b.x, b.y);
        const unsigned long long p67 = pack2(b.z, b.w);

        // Sum h^2 over this lane's elements
        unsigned long long s2 = fma2(p01, p01, mul2(p23, p23));
        s2 = fma2(p45, p45, s2);
        s2 = fma2(p67, p67, s2);
        float h2lo, h2hi; unpack2(s2, h2lo, h2hi);
        const float ph2 = h2lo + h2hi;

        const float t0 = t0k[k], t1 = t1k[k], v0 = v0k[k];
        const int xi = (int)(t0 * 14.0f);
        const int yi = (int)(t1 * 14.0f);
        const bool inb = (xi >= 0) && (xi <= COL - 1) && (yi >= 0) && (yi <= COL - 1);
        const bool vis = ((int)v0) == 1;
        const bool scat = vis && inb;         // warp-uniform

        if (scat) {
            // Sum h
            unsigned long long sh = add2(add2(p01, p23), add2(p45, p67));
            float shlo, shhi; unpack2(sh, shlo, shhi);
            const float ph = shlo + shhi;

            // Sum h*tt : per pair one gy scalar LDS + one gx LDS.64
            const char* gyrowB = reinterpret_cast<const char*>(sGT + yi * COL);
            const char* gxrowB = reinterpret_cast<const char*>(sGT + xi * COL);
            unsigned long long acc = 0ull;
            {
                const float gy = *(const float*)(gyrowB + ybO[0]);
                const unsigned long long gx2 = *(const unsigned long long*)(gxrowB + xbO[0]);
                acc = fma2(mul2(gx2, p01), pack2(gy, gy), acc);
            }
            {
                const float gy = *(const float*)(gyrowB + ybO[1]);
                const unsigned long long gx2 = *(const unsigned long long*)(gxrowB + xbO[1]);
                acc = fma2(mul2(gx2, p23), pack2(gy, gy), acc);
            }
            {
                const float gy = *(const float*)(gyrowB + ybO[2]);
                const unsigned long long gx2 = *(const unsigned long long*)(gxrowB + xbO[2]);
                acc = fma2(mul2(gx2, p45), pack2(gy, gy), acc);
            }
            {
                const float gy = *(const float*)(gyrowB + ybO[3]);
                const unsigned long long gx2 = *(const unsigned long long*)(gxrowB + xbO[3]);
                acc = fma2(mul2(gx2, p67), pack2(gy, gy), acc);
            }
            float htlo, hthi; unpack2(acc, htlo, hthi);
            const float phtt = htlo + hthi;

            const float mn = scmin[yi] * scmin[xi];
            const float mx = scmax[yi] * scmax[xi];
            const float inv = 1.0f / (mx - mn);
            const float nmi = -mn * inv;

            d1 += fmaf(-2.0f * inv, phtt, fmaf(-2.0f * nmi, ph, ph2));
            if (lane == 0) d1 += gp.T2[yi * COL + xi];

            // ---- argmax (visible joints only) ----
            float best = fmaxf(fmaxf(a.x, a.y), fmaxf(a.z, a.w));
            if (hasB) best = fmaxf(best, fmaxf(fmaxf(b.x, b.y), fmaxf(b.z, b.w)));
            int idx = 0x7fffffff;
            if (hasB) {
                idx = (b.w == best) ? (131 + base4) : idx;
                idx = (b.z == best) ? (130 + base4) : idx;
                idx = (b.y == best) ? (129 + base4) : idx;
                idx = (b.x == best) ? (128 + base4) : idx;
            }
            idx = (a.w == best) ? (3 + base4) : idx;
            idx = (a.z == best) ? (2 + base4) : idx;
            idx = (a.y == best) ? (1 + base4) : idx;
            idx = (a.x == best) ? (base4) : idx;

            unsigned u = __float_as_uint(best);
            unsigned mono = ((int)u < 0) ? ~u : (u | 0x80000000u);
            unsigned mmax = __reduce_max_sync(0xffffffffu, mono);
            int cand = (mono == mmax) ? idx : 0x7fffffff;
            int bidx = __reduce_min_sync(0xffffffffu, cand);
            if (lane == 0) sBidx[warp][k] = bidx;
        } else {
            // invisible / off-grid: d1 += ph2 - (row-0 part)
            float pr = 0.0f;
            if (lane < 4) {
                pr = fmaf(a.x, a.x, a.y * a.y);
                if (lane < 3) pr += fmaf(a.z, a.z, a.w * a.w);
            }
            d1 += ph2 - pr;
        }
    }

    // warp-reduce d1
    #pragma unroll
    for (int off = 16; off; off >>= 1)
        d1 += __shfl_xor_sync(0xffffffffu, d1, off);

    __syncwarp();

    // ---- phase B: gathers only for visible joints, lanes 0..3 ----
    float d2 = 0.0f, cntf = 0.0f;
    if (lane < JPW) {
        const int joint = joint0 + lane;
        const float t0 = t0k[lane];
        const float t1 = t1k[lane];
        const float v0 = v0k[lane];
        const int xi = (int)(t0 * 14.0f);
        const int yi = (int)(t1 * 14.0f);
        const bool inb = (xi >= 0) && (xi <= COL - 1) && (yi >= 0) && (yi <= COL - 1);
        const bool vis = ((int)v0) == 1;
        const float vef = (vis && !inb) ? 0.0f : v0;
        const float veI = (((int)vef) == 1) ? 1.0f : 0.0f;
        cntf = veI;

        if (vis && inb) {
            const int b2 = joint / NJ;
            const int j2 = joint - b2 * NJ;
            const int bidx = sBidx[warp][lane];
            const size_t ob = (size_t)b2 * (3 * NJ) * NPIX;
            const float ox = outp[ob + (size_t)(NJ + j2) * NPIX + bidx];
            const float oy = outp[ob + (size_t)(2 * NJ + j2) * NPIX + bidx];
            const int yc = bidx / COL;
            const int xc = bidx - yc * COL;
            const float px = (ox + (float)xc) * (1.0f / 14.0f);
            const float py = (oy + (float)yc) * (1.0f / 14.0f);
            const float dx = (px - t0) * vef;
            const float dy = (py - t1) * vef;
            d2 = fmaf(dx, dx, dy * dy);
        }
    }
    #pragma unroll
    for (int off = 1; off <= 2; off <<= 1) {
        d2   += __shfl_xor_sync(0xffffffffu, d2, off);
        cntf += __shfl_xor_sync(0xffffffffu, cntf, off);
    }

    if (lane == 0) { sred[warp][0] = d1; sred[warp][1] = d2; sred[warp][2] = cntf; }
    __syncthreads();

    if (tid == 0) {
        float a = 0.0f, bsum = 0.0f, c = 0.0f;
        #pragma unroll
        for (int w = 0; w < NWARPS; ++w) { a += sred[w][0]; bsum += sred[w][1]; c += sred[w][2]; }
        g_d1[blockIdx.x] = a;
        g_d2[blockIdx.x] = bsum;
        g_cnt[blockIdx.x] = c;
        __threadfence();
        unsigned old = atomicAdd(&g_ticket, 1u);
        s_last = (old == NBLOCKS - 1);
    }
    __syncthreads();

    // ---- last block: grid reduction ----
    if (s_last) {
        if (tid == 0) g_ticket = 0;          // net-zero per run
        __threadfence();
        double a = 0.0, bsum = 0.0, c = 0.0;
        for (int i = tid; i < NBLOCKS; i += THREADS) {
            a    += (double)g_d1[i];
            bsum += (double)g_d2[i];
            c    += (double)g_cnt[i];
        }
        #pragma unroll
        for (int off = 16; off; off >>= 1) {
            a    += __shfl_xor_sync(0xffffffffu, a, off);
            bsum += __shfl_xor_sync(0xffffffffu, bsum, off);
            c    += __shfl_xor_sync(0xffffffffu, c, off);
        }
        if (lane == 0) { dra[warp] = a; drb[warp] = bsum; drc[warp] = c; }
        __syncthreads();
        if (tid == 0) {
            double A = 0.0, B = 0.0, C = 0.0;
            #pragma unroll
            for (int w = 0; w < NWARPS; ++w) { A += dra[w]; B += drb[w]; C += drc[w]; }
            o[0] = (float)(A / C + B / C);   // n2 == cnt (v is a tiled 0/1 mask)
        }
    }
}

extern "C" void kernel_launch(void* const* d_in, const int* in_sizes, int n_in,
                              void* d_out, int out_size)
{
    const float* outp = (const float*)d_in[0];
    const float* t    = (const float*)d_in[1];
    const float* v    = (const float*)d_in[2];

    // Host-side Gaussian matrix + T2 table, matching the numpy reference.
    GParams gp;
    {
        double w[9], ws = 0.0;
        for (int k = 0; k < 9; ++k) { w[k] = exp(-0.5 * (double)((k - 4) * (k - 4))); ws += w[k]; }
        for (int k = 0; k < 9; ++k) w[k] /= ws;
        for (int r = 0; r < COL; ++r)
            for (int c = 0; c < COL; ++c) {
                double s = 0.0;
                for (int k = 0; k < 9; ++k) {
                    int rr = r + k;   // padded row, pad=4, 'symmetric'
                    int m = (rr < 4) ? (3 - rr) : ((rr > 17) ? (31 - rr) : (rr - 4));
                    if (m == c) s += w[k];
                }
                gp.GT[c * COL + r] = (float)s;
            }
        for (int c = 0; c < COL; ++c) {
            float mn = 1e30f, mx = -1e30f;
            for (int r = 0; r < COL; ++r) {
                float gv = gp.GT[c * COL + r];
                mn = fminf(mn, gv);
                mx = fmaxf(mx, gv);
            }
            gp.cmin[c] = mn;
            gp.cmax[c] = mx;
        }
        for (int yic = 0; yic < COL; ++yic)
            for (int xic = 0; xic < COL; ++xic) {
                float mn = gp.cmin[yic] * gp.cmin[xic];
                float mx = gp.cmax[yic] * gp.cmax[xic];
                float inv = 1.0f / (mx - mn);
                double s = 0.0;
                for (int y = 0; y < COL; ++y)
                    for (int x = 0; x < COL; ++x) {
                        float tt = gp.GT[yic * COL + y] * gp.GT[xic * COL + x];
                        float ttn = (tt - mn) * inv;
                        s += (double)ttn * (double)ttn;
                    }
                gp.T2[yic * COL + xic] = (float)s;
            }
    }

    main_kernel<<<NBLOCKS, THREADS>>>(outp, t, v, (float*)d_out, gp);
}

// round 9
// speedup vs baseline: 1.3184x; 1.2088x over previous
#include <cuda_runtime.h>
#include <math.h>

#define COL 14
#define NJ 14
#define NPIX 196
#define NB 8192
#define NJOINT (NB * NJ)                   // 114688
#define THREADS 256
#define NWARPS 8
#define JPW 8                              // joints per warp, in 4 groups of 2
#define NBLOCKS (NJOINT / (NWARPS * JPW))  // 1792 exactly

struct GParams {
    float GT[NPIX];     // GT[c*14+r] = G[r][c]  (row c of G^T)
    float cmin[COL];
    float cmax[COL];
    float T2[NPIX];     // T2[yic*14+xic] = sum over pixels of ttn^2
};

__device__ float    g_d1[NBLOCKS];
__device__ float    g_d2[NBLOCKS];
__device__ float    g_cnt[NBLOCKS];
__device__ unsigned g_ticket;   // zero-init at load; net-zero per run

// ---- packed f32x2 helpers (Blackwell) ----
__device__ __forceinline__ unsigned long long pack2(float lo, float hi) {
    unsigned long long r;
    asm("mov.b64 %0,{%1,%2};" : "=l"(r) : "f"(lo), "f"(hi));
    return r;
}
__device__ __forceinline__ void unpack2(unsigned long long p, float& lo, float& hi) {
    asm("mov.b64 {%0,%1},%2;" : "=f"(lo), "=f"(hi) : "l"(p));
}
__device__ __forceinline__ unsigned long long mul2(unsigned long long a, unsigned long long b) {
    unsigned long long r;
    asm("mul.rn.f32x2 %0,%1,%2;" : "=l"(r) : "l"(a), "l"(b));
    return r;
}
__device__ __forceinline__ unsigned long long add2(unsigned long long a, unsigned long long b) {
    unsigned long long r;
    asm("add.rn.f32x2 %0,%1,%2;" : "=l"(r) : "l"(a), "l"(b));
    return r;
}
__device__ __forceinline__ unsigned long long fma2(unsigned long long a, unsigned long long b,
                                                   unsigned long long c) {
    unsigned long long r;
    asm("fma.rn.f32x2 %0,%1,%2,%3;" : "=l"(r) : "l"(a), "l"(b), "l"(c));
    return r;
}

#define CP_ASYNC16(dst_u32, src_ptr) \
    asm volatile("cp.async.cg.shared.global [%0], [%1], 16;" \
                 :: "r"(dst_u32), "l"(src_ptr) : "memory")
#define CP_COMMIT() asm volatile("cp.async.commit_group;" ::: "memory")
#define CP_WAIT(n)  asm volatile("cp.async.wait_group %0;" :: "n"(n) : "memory")

__global__ __launch_bounds__(THREADS) void main_kernel(
    const float* __restrict__ outp,
    const float* __restrict__ t,
    const float* __restrict__ v,
    float* __restrict__ o,
    const GParams gp)
{
    // ring: per warp 2 slots x 2 joints x NPIX floats
    __shared__ __align__(16) float sH[NWARPS * 4 * NPIX];    // 25088 B
    __shared__ __align__(16) float sGT[NPIX];
    __shared__ float scmin[COL], scmax[COL];
    __shared__ float sred[NWARPS][3];
    __shared__ int   sBidx[NWARPS][JPW];
    __shared__ int   s_last;
    __shared__ double dra[NWARPS], drb[NWARPS], drc[NWARPS];

    const int tid = threadIdx.x;
    if (tid < NPIX) sGT[tid] = gp.GT[tid];
    if (tid < COL) { scmin[tid] = gp.cmin[tid]; scmax[tid] = gp.cmax[tid]; }
    __syncthreads();

    const int lane = tid & 31;
    const int warp = tid >> 5;
    const int gw = blockIdx.x * NWARPS + warp;
    const int joint0 = gw * JPW;
    const bool hasB = lane < 17;
    const int base4 = 4 * lane;
    const int baseByte = 16 * lane;

    const unsigned sHbase = (unsigned)__cvta_generic_to_shared(&sH[warp * (4 * NPIX)]);
    const float* sHw = &sH[warp * (4 * NPIX)];

    // ---- per-lane pair geometry ----
    int ybO[4], xbO[4];
    {
        #pragma unroll
        for (int p = 0; p < 4; ++p) {
            int e0 = (p < 2) ? (base4 + 2 * p) : (128 + base4 + 2 * (p - 2));
            if (p >= 2 && !hasB) e0 = 0;
            int y = e0 / COL;
            ybO[p] = y * 4;
            xbO[p] = (e0 - y * COL) * 4;
        }
    }

    // issue loads for group g (joints 2g, 2g+1) into slot
    auto issue = [&](int g, int slot) {
        #pragma unroll
        for (int i = 0; i < 2; ++i) {
            const int joint = joint0 + 2 * g + i;
            const int b2 = joint / NJ;
            const int j2 = joint - b2 * NJ;
            const char* hb = reinterpret_cast<const char*>(
                outp + ((size_t)b2 * (3 * NJ) + j2) * NPIX);
            const unsigned dst = sHbase + (slot * 2 + i) * (NPIX * 4);
            CP_ASYNC16(dst + baseByte, hb + baseByte);
            if (hasB) CP_ASYNC16(dst + 512 + baseByte, hb + 512 + baseByte);
        }
        CP_COMMIT();
    };

    float d1 = 0.0f;

    // compute group g from slot
    auto compute = [&](int g, int slot) {
        const float4 tv = *reinterpret_cast<const float4*>(t + 2 * (size_t)(joint0 + 2 * g));
        const float4 vv = *reinterpret_cast<const float4*>(v + 2 * (size_t)(joint0 + 2 * g));
        #pragma unroll
        for (int i = 0; i < 2; ++i) {
            const float* sj = sHw + (slot * 2 + i) * NPIX;
            const float4 a = *reinterpret_cast<const float4*>(sj + base4);
            float4 b = make_float4(0.0f, 0.0f, 0.0f, 0.0f);
            if (hasB) b = *reinterpret_cast<const float4*>(sj + 128 + base4);

            const unsigned long long p01 = pack2(a.x, a.y);
            const unsigned long long p23 = pack2(a.z, a.w);
            const unsigned long long p45 = pack2(b.x, b.y);
            const unsigned long long p67 = pack2(b.z, b.w);

            unsigned long long s2 = fma2(p01, p01, mul2(p23, p23));
            s2 = fma2(p45, p45, s2);
            s2 = fma2(p67, p67, s2);
            float h2lo, h2hi; unpack2(s2, h2lo, h2hi);
            const float ph2 = h2lo + h2hi;

            const float t0 = i ? tv.z : tv.x;
            const float t1 = i ? tv.w : tv.y;
            const float v0 = i ? vv.z : vv.x;
            const int xi = (int)(t0 * 14.0f);
            const int yi = (int)(t1 * 14.0f);
            const bool inb = (xi >= 0) && (xi <= COL - 1) && (yi >= 0) && (yi <= COL - 1);
            const bool vis = ((int)v0) == 1;
            const bool scat = vis && inb;       // warp-uniform

            if (scat) {
                unsigned long long sh = add2(add2(p01, p23), add2(p45, p67));
                float shlo, shhi; unpack2(sh, shlo, shhi);
                const float ph = shlo + shhi;

                const char* gyrowB = reinterpret_cast<const char*>(sGT + yi * COL);
                const char* gxrowB = reinterpret_cast<const char*>(sGT + xi * COL);
                unsigned long long acc = 0ull;
                {
                    const float gy = *(const float*)(gyrowB + ybO[0]);
                    const unsigned long long gx2 = *(const unsigned long long*)(gxrowB + xbO[0]);
                    acc = fma2(mul2(gx2, p01), pack2(gy, gy), acc);
                }
                {
                    const float gy = *(const float*)(gyrowB + ybO[1]);
                    const unsigned long long gx2 = *(const unsigned long long*)(gxrowB + xbO[1]);
                    acc = fma2(mul2(gx2, p23), pack2(gy, gy), acc);
                }
                {
                    const float gy = *(const float*)(gyrowB + ybO[2]);
                    const unsigned long long gx2 = *(const unsigned long long*)(gxrowB + xbO[2]);
                    acc = fma2(mul2(gx2, p45), pack2(gy, gy), acc);
                }
                {
                    const float gy = *(const float*)(gyrowB + ybO[3]);
                    const unsigned long long gx2 = *(const unsigned long long*)(gxrowB + xbO[3]);
                    acc = fma2(mul2(gx2, p67), pack2(gy, gy), acc);
                }
                float htlo, hthi; unpack2(acc, htlo, hthi);
                const float phtt = htlo + hthi;

                const float mn = scmin[yi] * scmin[xi];
                const float mx = scmax[yi] * scmax[xi];
                const float inv = 1.0f / (mx - mn);
                const float nmi = -mn * inv;

                d1 += fmaf(-2.0f * inv, phtt, fmaf(-2.0f * nmi, ph, ph2));
                if (lane == 0) d1 += gp.T2[yi * COL + xi];

                float best = fmaxf(fmaxf(a.x, a.y), fmaxf(a.z, a.w));
                if (hasB) best = fmaxf(best, fmaxf(fmaxf(b.x, b.y), fmaxf(b.z, b.w)));
                int idx = 0x7fffffff;
                if (hasB) {
                    idx = (b.w == best) ? (131 + base4) : idx;
                    idx = (b.z == best) ? (130 + base4) : idx;
                    idx = (b.y == best) ? (129 + base4) : idx;
                    idx = (b.x == best) ? (128 + base4) : idx;
                }
                idx = (a.w == best) ? (3 + base4) : idx;
                idx = (a.z == best) ? (2 + base4) : idx;
                idx = (a.y == best) ? (1 + base4) : idx;
                idx = (a.x == best) ? (base4) : idx;

                unsigned u = __float_as_uint(best);
                unsigned mono = ((int)u < 0) ? ~u : (u | 0x80000000u);
                unsigned mmax = __reduce_max_sync(0xffffffffu, mono);
                int cand = (mono == mmax) ? idx : 0x7fffffff;
                int bidx = __reduce_min_sync(0xffffffffu, cand);
                if (lane == 0) sBidx[warp][2 * g + i] = bidx;
            } else {
                float pr = 0.0f;
                if (lane < 4) {
                    pr = fmaf(a.x, a.x, a.y * a.y);
                    if (lane < 3) pr += fmaf(a.z, a.z, a.w * a.w);
                }
                d1 += ph2 - pr;
            }
        }
    };

    // ---- pipelined schedule: memory stays busy under compute ----
    issue(0, 0); issue(1, 1);
    CP_WAIT(1); compute(0, 0); issue(2, 0);
    CP_WAIT(1); compute(1, 1); issue(3, 1);
    CP_WAIT(1); compute(2, 0);
    CP_WAIT(0); compute(3, 1);

    // warp-reduce d1
    #pragma unroll
    for (int off = 16; off; off >>= 1)
        d1 += __shfl_xor_sync(0xffffffffu, d1, off);

    __syncwarp();

    // ---- phase B: gathers for visible joints, lanes 0..7 (one joint each) ----
    float d2 = 0.0f, cntf = 0.0f;
    if (lane < JPW) {
        const int joint = joint0 + lane;
        const float t0 = t[2 * joint];
        const float t1 = t[2 * joint + 1];
        const float v0 = v[2 * joint];
        const int xi = (int)(t0 * 14.0f);
        const int yi = (int)(t1 * 14.0f);
        const bool inb = (xi >= 0) && (xi <= COL - 1) && (yi >= 0) && (yi <= COL - 1);
        const bool vis = ((int)v0) == 1;
        const float vef = (vis && !inb) ? 0.0f : v0;
        const float veI = (((int)vef) == 1) ? 1.0f : 0.0f;
        cntf = veI;

        if (vis && inb) {
            const int b2 = joint / NJ;
            const int j2 = joint - b2 * NJ;
            const int bidx = sBidx[warp][lane];
            const size_t ob = (size_t)b2 * (3 * NJ) * NPIX;
            const float ox = outp[ob + (size_t)(NJ + j2) * NPIX + bidx];
            const float oy = outp[ob + (size_t)(2 * NJ + j2) * NPIX + bidx];
            const int yc = bidx / COL;
            const int xc = bidx - yc * COL;
            const float px = (ox + (float)xc) * (1.0f / 14.0f);
            const float py = (oy + (float)yc) * (1.0f / 14.0f);
            const float dx = (px - t0) * vef;
            const float dy = (py - t1) * vef;
            d2 = fmaf(dx, dx, dy * dy);
        }
    }
    #pragma unroll
    for (int off = 1; off <= 4; off <<= 1) {
        d2   += __shfl_xor_sync(0xffffffffu, d2, off);
        cntf += __shfl_xor_sync(0xffffffffu, cntf, off);
    }

    if (lane == 0) { sred[warp][0] = d1; sred[warp][1] = d2; sred[warp][2] = cntf; }
    __syncthreads();

    if (tid == 0) {
        float a = 0.0f, bsum = 0.0f, c = 0.0f;
        #pragma unroll
        for (int w = 0; w < NWARPS; ++w) { a += sred[w][0]; bsum += sred[w][1]; c += sred[w][2]; }
        g_d1[blockIdx.x] = a;
        g_d2[blockIdx.x] = bsum;
        g_cnt[blockIdx.x] = c;
        __threadfence();
        unsigned old = atomicAdd(&g_ticket, 1u);
        s_last = (old == NBLOCKS - 1);
    }
    __syncthreads();

    // ---- last block: grid reduction ----
    if (s_last) {
        if (tid == 0) g_ticket = 0;          // net-zero per run
        __threadfence();
        double a = 0.0, bsum = 0.0, c = 0.0;
        for (int i = tid; i < NBLOCKS; i += THREADS) {
            a    += (double)g_d1[i];
            bsum += (double)g_d2[i];
            c    += (double)g_cnt[i];
        }
        #pragma unroll
        for (int off = 16; off; off >>= 1) {
            a    += __shfl_xor_sync(0xffffffffu, a, off);
            bsum += __shfl_xor_sync(0xffffffffu, bsum, off);
            c    += __shfl_xor_sync(0xffffffffu, c, off);
        }
        if (lane == 0) { dra[warp] = a; drb[warp] = bsum; drc[warp] = c; }
        __syncthreads();
        if (tid == 0) {
            double A = 0.0, B = 0.0, C = 0.0;
            #pragma unroll
            for (int w = 0; w < NWARPS; ++w) { A += dra[w]; B += drb[w]; C += drc[w]; }
            o[0] = (float)(A / C + B / C);   // n2 == cnt (v is a tiled 0/1 mask)
        }
    }
}

extern "C" void kernel_launch(void* const* d_in, const int* in_sizes, int n_in,
                              void* d_out, int out_size)
{
    const float* outp = (const float*)d_in[0];
    const float* t    = (const float*)d_in[1];
    const float* v    = (const float*)d_in[2];

    // Host-side Gaussian matrix + T2 table, matching the numpy reference.
    GParams gp;
    {
        double w[9], ws = 0.0;
        for (int k = 0; k < 9; ++k) { w[k] = exp(-0.5 * (double)((k - 4) * (k - 4))); ws += w[k]; }
        for (int k = 0; k < 9; ++k) w[k] /= ws;
        for (int r = 0; r < COL; ++r)
            for (int c = 0; c < COL; ++c) {
                double s = 0.0;
                for (int k = 0; k < 9; ++k) {
                    int rr = r + k;   // padded row, pad=4, 'symmetric'
                    int m = (rr < 4) ? (3 - rr) : ((rr > 17) ? (31 - rr) : (rr - 4));
                    if (m == c) s += w[k];
                }
                gp.GT[c * COL + r] = (float)s;
            }
        for (int c = 0; c < COL; ++c) {
            float mn = 1e30f, mx = -1e30f;
            for (int r = 0; r < COL; ++r) {
                float gv = gp.GT[c * COL + r];
                mn = fminf(mn, gv);
                mx = fmaxf(mx, gv);
            }
            gp.cmin[c] = mn;
            gp.cmax[c] = mx;
        }
        for (int yic = 0; yic < COL; ++yic)
            for (int xic = 0; xic < COL; ++xic) {
                float mn = gp.cmin[yic] * gp.cmin[xic];
                float mx = gp.cmax[yic] * gp.cmax[xic];
                float inv = 1.0f / (mx - mn);
                double s = 0.0;
                for (int y = 0; y < COL; ++y)
                    for (int x = 0; x < COL; ++x) {
                        float tt = gp.GT[yic * COL + y] * gp.GT[xic * COL + x];
                        float ttn = (tt - mn) * inv;
                        s += (double)ttn * (double)ttn;
                    }
                gp.T2[yic * COL + xic] = (float)s;
            }
    }

    main_kernel<<<NBLOCKS, THREADS>>>(outp, t, v, (float*)d_out, gp);
}

// round 11
// speedup vs baseline: 1.3801x; 1.0468x over previous
#include <cuda_runtime.h>
#include <math.h>

#define COL 14
#define NJ 14
#define NPIX 196
#define NB 8192
#define NJOINT (NB * NJ)                   // 114688
#define THREADS 256
#define NWARPS 8
#define JPW 8                              // joints per warp, 4 groups of 2
#define NBLOCKS (NJOINT / (NWARPS * JPW))  // 1792 exactly
#define SLOTS 3

struct GParams {
    float GT[NPIX];     // GT[c*14+r] = G[r][c]  (row c of G^T)
    float cmin[COL];
    float cmax[COL];
    float T2[NPIX];     // T2[yic*14+xic] = sum over pixels of ttn^2
};

__device__ float    g_d1[NBLOCKS];
__device__ float    g_d2[NBLOCKS];
__device__ float    g_cnt[NBLOCKS];
__device__ unsigned g_ticket;   // zero-init at load; net-zero per run

// ---- packed f32x2 helpers (Blackwell) ----
__device__ __forceinline__ unsigned long long pack2(float lo, float hi) {
    unsigned long long r;
    asm("mov.b64 %0,{%1,%2};" : "=l"(r) : "f"(lo), "f"(hi));
    return r;
}
__device__ __forceinline__ void unpack2(unsigned long long p, float& lo, float& hi) {
    asm("mov.b64 {%0,%1},%2;" : "=f"(lo), "=f"(hi) : "l"(p));
}
__device__ __forceinline__ unsigned long long mul2(unsigned long long a, unsigned long long b) {
    unsigned long long r;
    asm("mul.rn.f32x2 %0,%1,%2;" : "=l"(r) : "l"(a), "l"(b));
    return r;
}
__device__ __forceinline__ unsigned long long add2(unsigned long long a, unsigned long long b) {
    unsigned long long r;
    asm("add.rn.f32x2 %0,%1,%2;" : "=l"(r) : "l"(a), "l"(b));
    return r;
}
__device__ __forceinline__ unsigned long long fma2(unsigned long long a, unsigned long long b,
                                                   unsigned long long c) {
    unsigned long long r;
    asm("fma.rn.f32x2 %0,%1,%2,%3;" : "=l"(r) : "l"(a), "l"(b), "l"(c));
    return r;
}

#define CP_ASYNC16(dst_u32, src_ptr) \
    asm volatile("cp.async.cg.shared.global [%0], [%1], 16;" \
                 :: "r"(dst_u32), "l"(src_ptr) : "memory")
#define CP_COMMIT() asm volatile("cp.async.commit_group;" ::: "memory")
#define CP_WAIT(n)  asm volatile("cp.async.wait_group %0;" :: "n"(n) : "memory")

__global__ __launch_bounds__(THREADS) void main_kernel(
    const float* __restrict__ outp,
    const float* __restrict__ t,
    const float* __restrict__ v,
    float* __restrict__ o,
    const GParams gp)
{
    // ring: per warp SLOTS slots x 2 joints x NPIX floats
    __shared__ __align__(16) float sH[NWARPS * SLOTS * 2 * NPIX];   // 37632 B
    __shared__ __align__(16) float sGT[NPIX];
    __shared__ float scmin[COL], scmax[COL];
    __shared__ float sred[NWARPS][3];
    __shared__ int   sBidx[NWARPS][JPW];
    __shared__ int   s_last;
    __shared__ double dra[NWARPS], drb[NWARPS], drc[NWARPS];

    const int tid = threadIdx.x;
    if (tid < NPIX) sGT[tid] = gp.GT[tid];
    if (tid < COL) { scmin[tid] = gp.cmin[tid]; scmax[tid] = gp.cmax[tid]; }
    __syncthreads();

    const int lane = tid & 31;
    const int warp = tid >> 5;
    const int gw = blockIdx.x * NWARPS + warp;
    const int joint0 = gw * JPW;
    const bool hasB = lane < 17;
    const int base4 = 4 * lane;
    const int baseByte = 16 * lane;

    const unsigned sHbase =
        (unsigned)__cvta_generic_to_shared(&sH[warp * (SLOTS * 2 * NPIX)]);
    const float* sHw = &sH[warp * (SLOTS * 2 * NPIX)];

    // ---- per-lane pair geometry ----
    int ybO[4], xbO[4];
    {
        #pragma unroll
        for (int p = 0; p < 4; ++p) {
            int e0 = (p < 2) ? (base4 + 2 * p) : (128 + base4 + 2 * (p - 2));
            if (p >= 2 && !hasB) e0 = 0;
            int y = e0 / COL;
            ybO[p] = y * 4;
            xbO[p] = (e0 - y * COL) * 4;
        }
    }

    // issue loads for group g (joints 2g, 2g+1) into slot
    auto issue = [&](int g, int slot) {
        #pragma unroll
        for (int i = 0; i < 2; ++i) {
            const int joint = joint0 + 2 * g + i;
            const int b2 = joint / NJ;
            const int j2 = joint - b2 * NJ;
            const char* hb = reinterpret_cast<const char*>(
                outp + ((size_t)b2 * (3 * NJ) + j2) * NPIX);
            const unsigned dst = sHbase + (slot * 2 + i) * (NPIX * 4);
            CP_ASYNC16(dst + baseByte, hb + baseByte);
            if (hasB) CP_ASYNC16(dst + 512 + baseByte, hb + 512 + baseByte);
        }
        CP_COMMIT();
    };

    float d1 = 0.0f;

    // compute group g from slot
    auto compute = [&](int g, int slot) {
        const float4 tv = *reinterpret_cast<const float4*>(t + 2 * (size_t)(joint0 + 2 * g));
        const float4 vv = *reinterpret_cast<const float4*>(v + 2 * (size_t)(joint0 + 2 * g));
        #pragma unroll
        for (int i = 0; i < 2; ++i) {
            const float* sj = sHw + (slot * 2 + i) * NPIX;
            const float4 a = *reinterpret_cast<const float4*>(sj + base4);
            float4 b = make_float4(0.0f, 0.0f, 0.0f, 0.0f);
            if (hasB) b = *reinterpret_cast<const float4*>(sj + 128 + base4);

            const unsigned long long p01 = pack2(a.x, a.y);
            const unsigned long long p23 = pack2(a.z, a.w);
            const unsigned long long p45 = pack2(b.x, b.y);
            const unsigned long long p67 = pack2(b.z, b.w);

            unsigned long long s2 = fma2(p01, p01, mul2(p23, p23));
            s2 = fma2(p45, p45, s2);
            s2 = fma2(p67, p67, s2);
            float h2lo, h2hi; unpack2(s2, h2lo, h2hi);
            const float ph2 = h2lo + h2hi;

            const float t0 = i ? tv.z : tv.x;
            const float t1 = i ? tv.w : tv.y;
            const float v0 = i ? vv.z : vv.x;
            const int xi = (int)(t0 * 14.0f);
            const int yi = (int)(t1 * 14.0f);
            const bool inb = (xi >= 0) && (xi <= COL - 1) && (yi >= 0) && (yi <= COL - 1);
            const bool vis = ((int)v0) == 1;
            const bool scat = vis && inb;       // warp-uniform

            if (scat) {
                unsigned long long sh = add2(add2(p01, p23), add2(p45, p67));
                float shlo, shhi; unpack2(sh, shlo, shhi);
                const float ph = shlo + shhi;

                const char* gyrowB = reinterpret_cast<const char*>(sGT + yi * COL);
                const char* gxrowB = reinterpret_cast<const char*>(sGT + xi * COL);
                unsigned long long acc = 0ull;
                {
                    const float gy = *(const float*)(gyrowB + ybO[0]);
                    const unsigned long long gx2 = *(const unsigned long long*)(gxrowB + xbO[0]);
                    acc = fma2(mul2(gx2, p01), pack2(gy, gy), acc);
                }
                {
                    const float gy = *(const float*)(gyrowB + ybO[1]);
                    const unsigned long long gx2 = *(const unsigned long long*)(gxrowB + xbO[1]);
                    acc = fma2(mul2(gx2, p23), pack2(gy, gy), acc);
                }
                {
                    const float gy = *(const float*)(gyrowB + ybO[2]);
                    const unsigned long long gx2 = *(const unsigned long long*)(gxrowB + xbO[2]);
                    acc = fma2(mul2(gx2, p45), pack2(gy, gy), acc);
                }
                {
                    const float gy = *(const float*)(gyrowB + ybO[3]);
                    const unsigned long long gx2 = *(const unsigned long long*)(gxrowB + xbO[3]);
                    acc = fma2(mul2(gx2, p67), pack2(gy, gy), acc);
                }
                float htlo, hthi; unpack2(acc, htlo, hthi);
                const float phtt = htlo + hthi;

                const float mn = scmin[yi] * scmin[xi];
                const float mx = scmax[yi] * scmax[xi];
                const float inv = 1.0f / (mx - mn);
                const float nmi = -mn * inv;

                d1 += fmaf(-2.0f * inv, phtt, fmaf(-2.0f * nmi, ph, ph2));
                if (lane == 0) d1 += gp.T2[yi * COL + xi];

                float best = fmaxf(fmaxf(a.x, a.y), fmaxf(a.z, a.w));
                if (hasB) best = fmaxf(best, fmaxf(fmaxf(b.x, b.y), fmaxf(b.z, b.w)));
                int idx = 0x7fffffff;
                if (hasB) {
                    idx = (b.w == best) ? (131 + base4) : idx;
                    idx = (b.z == best) ? (130 + base4) : idx;
                    idx = (b.y == best) ? (129 + base4) : idx;
                    idx = (b.x == best) ? (128 + base4) : idx;
                }
                idx = (a.w == best) ? (3 + base4) : idx;
                idx = (a.z == best) ? (2 + base4) : idx;
                idx = (a.y == best) ? (1 + base4) : idx;
                idx = (a.x == best) ? (base4) : idx;

                unsigned u = __float_as_uint(best);
                unsigned mono = ((int)u < 0) ? ~u : (u | 0x80000000u);
                unsigned mmax = __reduce_max_sync(0xffffffffu, mono);
                int cand = (mono == mmax) ? idx : 0x7fffffff;
                int bidx = __reduce_min_sync(0xffffffffu, cand);
                if (lane == 0) sBidx[warp][2 * g + i] = bidx;
            } else {
                float pr = 0.0f;
                if (lane < 4) {
                    pr = fmaf(a.x, a.x, a.y * a.y);
                    if (lane < 3) pr += fmaf(a.z, a.z, a.w * a.w);
                }
                d1 += ph2 - pr;
            }
        }
    };

    // ---- 3-deep pipelined schedule: 2-3 groups in flight per compute stage ----
    issue(0, 0); issue(1, 1); issue(2, 2);
    CP_WAIT(2); compute(0, 0); issue(3, 0);
    CP_WAIT(2); compute(1, 1);
    CP_WAIT(1); compute(2, 2);
    CP_WAIT(0); compute(3, 0);

    // warp-reduce d1
    #pragma unroll
    for (int off = 16; off; off >>= 1)
        d1 += __shfl_xor_sync(0xffffffffu, d1, off);

    __syncwarp();

    // ---- phase B: gathers for visible joints, lanes 0..7 (one joint each) ----
    float d2 = 0.0f, cntf = 0.0f;
    if (lane < JPW) {
        const int joint = joint0 + lane;
        const float t0 = t[2 * joint];
        const float t1 = t[2 * joint + 1];
        const float v0 = v[2 * joint];
        const int xi = (int)(t0 * 14.0f);
        const int yi = (int)(t1 * 14.0f);
        const bool inb = (xi >= 0) && (xi <= COL - 1) && (yi >= 0) && (yi <= COL - 1);
        const bool vis = ((int)v0) == 1;
        const float vef = (vis && !inb) ? 0.0f : v0;
        const float veI = (((int)vef) == 1) ? 1.0f : 0.0f;
        cntf = veI;

        if (vis && inb) {
            const int b2 = joint / NJ;
            const int j2 = joint - b2 * NJ;
            const int bidx = sBidx[warp][lane];
            const size_t ob = (size_t)b2 * (3 * NJ) * NPIX;
            const float ox = outp[ob + (size_t)(NJ + j2) * NPIX + bidx];
            const float oy = outp[ob + (size_t)(2 * NJ + j2) * NPIX + bidx];
            const int yc = bidx / COL;
            const int xc = bidx - yc * COL;
            const float px = (ox + (float)xc) * (1.0f / 14.0f);
            const float py = (oy + (float)yc) * (1.0f / 14.0f);
            const float dx = (px - t0) * vef;
            const float dy = (py - t1) * vef;
            d2 = fmaf(dx, dx, dy * dy);
        }
    }
    #pragma unroll
    for (int off = 1; off <= 4; off <<= 1) {
        d2   += __shfl_xor_sync(0xffffffffu, d2, off);
        cntf += __shfl_xor_sync(0xffffffffu, cntf, off);
    }

    if (lane == 0) { sred[warp][0] = d1; sred[warp][1] = d2; sred[warp][2] = cntf; }
    __syncthreads();

    if (tid == 0) {
        float a = 0.0f, bsum = 0.0f, c = 0.0f;
        #pragma unroll
        for (int w = 0; w < NWARPS; ++w) { a += sred[w][0]; bsum += sred[w][1]; c += sred[w][2]; }
        g_d1[blockIdx.x] = a;
        g_d2[blockIdx.x] = bsum;
        g_cnt[blockIdx.x] = c;
        __threadfence();
        unsigned old = atomicAdd(&g_ticket, 1u);
        s_last = (old == NBLOCKS - 1);
    }
    __syncthreads();

    // ---- last block: grid reduction ----
    if (s_last) {
        if (tid == 0) g_ticket = 0;          // net-zero per run
        __threadfence();
        double a = 0.0, bsum = 0.0, c = 0.0;
        for (int i = tid; i < NBLOCKS; i += THREADS) {
            a    += (double)g_d1[i];
            bsum += (double)g_d2[i];
            c    += (double)g_cnt[i];
        }
        #pragma unroll
        for (int off = 16; off; off >>= 1) {
            a    += __shfl_xor_sync(0xffffffffu, a, off);
            bsum += __shfl_xor_sync(0xffffffffu, bsum, off);
            c    += __shfl_xor_sync(0xffffffffu, c, off);
        }
        if (lane == 0) { dra[warp] = a; drb[warp] = bsum; drc[warp] = c; }
        __syncthreads();
        if (tid == 0) {
            double A = 0.0, B = 0.0, C = 0.0;
            #pragma unroll
            for (int w = 0; w < NWARPS; ++w) { A += dra[w]; B += drb[w]; C += drc[w]; }
            o[0] = (float)(A / C + B / C);   // n2 == cnt (v is a tiled 0/1 mask)
        }
    }
}

extern "C" void kernel_launch(void* const* d_in, const int* in_sizes, int n_in,
                              void* d_out, int out_size)
{
    const float* outp = (const float*)d_in[0];
    const float* t    = (const float*)d_in[1];
    const float* v    = (const float*)d_in[2];

    // Host-side Gaussian matrix + T2 table, matching the numpy reference.
    GParams gp;
    {
        double w[9], ws = 0.0;
        for (int k = 0; k < 9; ++k) { w[k] = exp(-0.5 * (double)((k - 4) * (k - 4))); ws += w[k]; }
        for (int k = 0; k < 9; ++k) w[k] /= ws;
        for (int r = 0; r < COL; ++r)
            for (int c = 0; c < COL; ++c) {
                double s = 0.0;
                for (int k = 0; k < 9; ++k) {
                    int rr = r + k;   // padded row, pad=4, 'symmetric'
                    int m = (rr < 4) ? (3 - rr) : ((rr > 17) ? (31 - rr) : (rr - 4));
                    if (m == c) s += w[k];
                }
                gp.GT[c * COL + r] = (float)s;
            }
        for (int c = 0; c < COL; ++c) {
            float mn = 1e30f, mx = -1e30f;
            for (int r = 0; r < COL; ++r) {
                float gv = gp.GT[c * COL + r];
                mn = fminf(mn, gv);
                mx = fmaxf(mx, gv);
            }
            gp.cmin[c] = mn;
            gp.cmax[c] = mx;
        }
        for (int yic = 0; yic < COL; ++yic)
            for (int xic = 0; xic < COL; ++xic) {
                float mn = gp.cmin[yic] * gp.cmin[xic];
                float mx = gp.cmax[yic] * gp.cmax[xic];
                float inv = 1.0f / (mx - mn);
                double s = 0.0;
                for (int y = 0; y < COL; ++y)
                    for (int x = 0; x < COL; ++x) {
                        float tt = gp.GT[yic * COL + y] * gp.GT[xic * COL + x];
                        float ttn = (tt - mn) * inv;
                        s += (double)ttn * (double)ttn;
                    }
                gp.T2[yic * COL + xic] = (float)s;
            }
    }

    main_kernel<<<NBLOCKS, THREADS>>>(outp, t, v, (float*)d_out, gp);
}

// round 12
// speedup vs baseline: 1.5788x; 1.1440x over previous
#include <cuda_runtime.h>
#include <math.h>

#define COL 14
#define NJ 14
#define NPIX 196
#define NB 8192
#define NJOINT (NB * NJ)                   // 114688
#define THREADS 256
#define NWARPS 8
#define GRID 608                           // ~152 SMs x 4 CTAs: single wave
#define WTOT (GRID * NWARPS)               // 4864 warps
#define NTASKS (NJOINT / 8)                // 14336 tasks of 8 joints
#define SLOTS 3

struct GParams {
    float GT[NPIX];     // GT[c*14+r] = G[r][c]
    float cmin[COL];
    float cmax[COL];
    float T2[NPIX];     // T2[yic*14+xic] = sum ttn^2
};

__device__ float    g_d1[GRID];
__device__ float    g_d2[GRID];
__device__ float    g_cnt[GRID];
__device__ unsigned g_ticket;   // zero-init at load; net-zero per run

// ---- packed f32x2 helpers ----
__device__ __forceinline__ unsigned long long pack2(float lo, float hi) {
    unsigned long long r;
    asm("mov.b64 %0,{%1,%2};" : "=l"(r) : "f"(lo), "f"(hi));
    return r;
}
__device__ __forceinline__ void unpack2(unsigned long long p, float& lo, float& hi) {
    asm("mov.b64 {%0,%1},%2;" : "=f"(lo), "=f"(hi) : "l"(p));
}
__device__ __forceinline__ unsigned long long mul2(unsigned long long a, unsigned long long b) {
    unsigned long long r;
    asm("mul.rn.f32x2 %0,%1,%2;" : "=l"(r) : "l"(a), "l"(b));
    return r;
}
__device__ __forceinline__ unsigned long long add2(unsigned long long a, unsigned long long b) {
    unsigned long long r;
    asm("add.rn.f32x2 %0,%1,%2;" : "=l"(r) : "l"(a), "l"(b));
    return r;
}
__device__ __forceinline__ unsigned long long fma2(unsigned long long a, unsigned long long b,
                                                   unsigned long long c) {
    unsigned long long r;
    asm("fma.rn.f32x2 %0,%1,%2,%3;" : "=l"(r) : "l"(a), "l"(b), "l"(c));
    return r;
}

#define CP_ASYNC16(dst_u32, src_ptr) \
    asm volatile("cp.async.cg.shared.global [%0], [%1], 16;" \
                 :: "r"(dst_u32), "l"(src_ptr) : "memory")
#define CP_COMMIT() asm volatile("cp.async.commit_group;" ::: "memory")
#define CP_WAIT(n)  asm volatile("cp.async.wait_group %0;" :: "n"(n) : "memory")

__global__ __launch_bounds__(THREADS) void main_kernel(
    const float* __restrict__ outp,
    const float* __restrict__ t,
    const float* __restrict__ v,
    float* __restrict__ o,
    const GParams gp)
{
    __shared__ __align__(16) float sH[NWARPS * SLOTS * 2 * NPIX];   // 37632 B
    __shared__ __align__(16) float sGT[NPIX];
    __shared__ float scmin[COL], scmax[COL];
    __shared__ float sred[NWARPS][3];
    __shared__ int   sBidx[NWARPS][32];
    __shared__ int   s_last;
    __shared__ double dra[NWARPS], drb[NWARPS], drc[NWARPS];

    const int tid = threadIdx.x;
    if (tid < NPIX) sGT[tid] = gp.GT[tid];
    if (tid < COL) { scmin[tid] = gp.cmin[tid]; scmax[tid] = gp.cmax[tid]; }
    __syncthreads();

    const int lane = tid & 31;
    const int warp = tid >> 5;
    const int gwarp = blockIdx.x * NWARPS + warp;
    const bool hasB = lane < 17;
    const int base4 = 4 * lane;
    const int baseByte = 16 * lane;

    // tasks: gwarp, gwarp+WTOT, gwarp+2*WTOT (if < NTASKS)
    const int ntask = (gwarp < NTASKS - 2 * WTOT) ? 3 : 2;
    const int ng = 4 * ntask;            // groups of 2 joints

    const unsigned sHbase =
        (unsigned)__cvta_generic_to_shared(&sH[warp * (SLOTS * 2 * NPIX)]);
    const float* sHw = &sH[warp * (SLOTS * 2 * NPIX)];

    // ---- per-lane pair geometry ----
    int ybO[4], xbO[4];
    {
        #pragma unroll
        for (int p = 0; p < 4; ++p) {
            int e0 = (p < 2) ? (base4 + 2 * p) : (128 + base4 + 2 * (p - 2));
            if (p >= 2 && !hasB) e0 = 0;
            int y = e0 / COL;
            ybO[p] = y * 4;
            xbO[p] = (e0 - y * COL) * 4;
        }
    }

    // group gg -> first joint of the pair
    auto group_joint0 = [&](int gg) {
        const int task = gg >> 2;
        return (gwarp + task * WTOT) * 8 + (gg & 3) * 2;
    };

    auto issue = [&](int gg, int slot) {
        const int j0 = group_joint0(gg);
        #pragma unroll
        for (int i = 0; i < 2; ++i) {
            const int joint = j0 + i;
            const int b2 = joint / NJ;
            const int j2 = joint - b2 * NJ;
            const char* hb = reinterpret_cast<const char*>(
                outp + ((size_t)b2 * (3 * NJ) + j2) * NPIX);
            const unsigned dst = sHbase + (slot * 2 + i) * (NPIX * 4);
            CP_ASYNC16(dst + baseByte, hb + baseByte);
            if (hasB) CP_ASYNC16(dst + 512 + baseByte, hb + 512 + baseByte);
        }
        CP_COMMIT();
    };

    float d1 = 0.0f;

    auto compute = [&](int gg, int slot) {
        const int j0 = group_joint0(gg);
        const int bslot = (gg >> 2) * 8 + (gg & 3) * 2;  // sBidx index base
        const float4 tv = *reinterpret_cast<const float4*>(t + 2 * (size_t)j0);
        const float4 vv = *reinterpret_cast<const float4*>(v + 2 * (size_t)j0);
        #pragma unroll
        for (int i = 0; i < 2; ++i) {
            const float* sj = sHw + (slot * 2 + i) * NPIX;
            const float4 a = *reinterpret_cast<const float4*>(sj + base4);
            float4 b = make_float4(0.0f, 0.0f, 0.0f, 0.0f);
            if (hasB) b = *reinterpret_cast<const float4*>(sj + 128 + base4);

            const unsigned long long p01 = pack2(a.x, a.y);
            const unsigned long long p23 = pack2(a.z, a.w);
            const unsigned long long p45 = pack2(b.x, b.y);
            const unsigned long long p67 = pack2(b.z, b.w);

            unsigned long long s2 = fma2(p01, p01, mul2(p23, p23));
            s2 = fma2(p45, p45, s2);
            s2 = fma2(p67, p67, s2);
            float h2lo, h2hi; unpack2(s2, h2lo, h2hi);
            const float ph2 = h2lo + h2hi;

            const float t0 = i ? tv.z : tv.x;
            const float t1 = i ? tv.w : tv.y;
            const float v0 = i ? vv.z : vv.x;
            const int xi = (int)(t0 * 14.0f);
            const int yi = (int)(t1 * 14.0f);
            const bool inb = (xi >= 0) && (xi <= COL - 1) && (yi >= 0) && (yi <= COL - 1);
            const bool vis = ((int)v0) == 1;
            const bool scat = vis && inb;       // warp-uniform

            if (scat) {
                unsigned long long sh = add2(add2(p01, p23), add2(p45, p67));
                float shlo, shhi; unpack2(sh, shlo, shhi);
                const float ph = shlo + shhi;

                const char* gyrowB = reinterpret_cast<const char*>(sGT + yi * COL);
                const char* gxrowB = reinterpret_cast<const char*>(sGT + xi * COL);
                unsigned long long acc = 0ull;
                {
                    const float gy = *(const float*)(gyrowB + ybO[0]);
                    const unsigned long long gx2 = *(const unsigned long long*)(gxrowB + xbO[0]);
                    acc = fma2(mul2(gx2, p01), pack2(gy, gy), acc);
                }
                {
                    const float gy = *(const float*)(gyrowB + ybO[1]);
                    const unsigned long long gx2 = *(const unsigned long long*)(gxrowB + xbO[1]);
                    acc = fma2(mul2(gx2, p23), pack2(gy, gy), acc);
                }
                {
                    const float gy = *(const float*)(gyrowB + ybO[2]);
                    const unsigned long long gx2 = *(const unsigned long long*)(gxrowB + xbO[2]);
                    acc = fma2(mul2(gx2, p45), pack2(gy, gy), acc);
                }
                {
                    const float gy = *(const float*)(gyrowB + ybO[3]);
                    const unsigned long long gx2 = *(const unsigned long long*)(gxrowB + xbO[3]);
                    acc = fma2(mul2(gx2, p67), pack2(gy, gy), acc);
                }
                float htlo, hthi; unpack2(acc, htlo, hthi);
                const float phtt = htlo + hthi;

                const float mn = scmin[yi] * scmin[xi];
                const float mx = scmax[yi] * scmax[xi];
                const float inv = 1.0f / (mx - mn);
                const float nmi = -mn * inv;

                d1 += fmaf(-2.0f * inv, phtt, fmaf(-2.0f * nmi, ph, ph2));
                if (lane == 0) d1 += gp.T2[yi * COL + xi];

                float best = fmaxf(fmaxf(a.x, a.y), fmaxf(a.z, a.w));
                if (hasB) best = fmaxf(best, fmaxf(fmaxf(b.x, b.y), fmaxf(b.z, b.w)));
                int idx = 0x7fffffff;
                if (hasB) {
                    idx = (b.w == best) ? (131 + base4) : idx;
                    idx = (b.z == best) ? (130 + base4) : idx;
                    idx = (b.y == best) ? (129 + base4) : idx;
                    idx = (b.x == best) ? (128 + base4) : idx;
                }
                idx = (a.w == best) ? (3 + base4) : idx;
                idx = (a.z == best) ? (2 + base4) : idx;
                idx = (a.y == best) ? (1 + base4) : idx;
                idx = (a.x == best) ? (base4) : idx;

                unsigned u = __float_as_uint(best);
                unsigned mono = ((int)u < 0) ? ~u : (u | 0x80000000u);
                unsigned mmax = __reduce_max_sync(0xffffffffu, mono);
                int cand = (mono == mmax) ? idx : 0x7fffffff;
                int bidx = __reduce_min_sync(0xffffffffu, cand);
                if (lane == 0) sBidx[warp][bslot + i] = bidx;
            } else {
                float pr = 0.0f;
                if (lane < 4) {
                    pr = fmaf(a.x, a.x, a.y * a.y);
                    if (lane < 3) pr += fmaf(a.z, a.z, a.w * a.w);
                }
                d1 += ph2 - pr;
            }
        }
    };

    // ---- continuous 3-slot pipeline over all ng groups ----
    issue(0, 0); issue(1, 1); issue(2, 2);
    {
        int slot = 0;
        for (int gg = 0; gg + 3 < ng; ++gg) {
            CP_WAIT(2);
            compute(gg, slot);
            issue(gg + 3, slot);
            slot = (slot == 2) ? 0 : slot + 1;
        }
        CP_WAIT(2); compute(ng - 3, slot); slot = (slot == 2) ? 0 : slot + 1;
        CP_WAIT(1); compute(ng - 2, slot); slot = (slot == 2) ? 0 : slot + 1;
        CP_WAIT(0); compute(ng - 1, slot);
    }

    // warp-reduce d1
    #pragma unroll
    for (int off = 16; off; off >>= 1)
        d1 += __shfl_xor_sync(0xffffffffu, d1, off);

    __syncwarp();

    // ---- phase B: one joint per lane (up to 24) ----
    float d2 = 0.0f, cntf = 0.0f;
    if (lane < ntask * 8) {
        const int joint = (gwarp + (lane >> 3) * WTOT) * 8 + (lane & 7);
        const float t0 = t[2 * joint];
        const float t1 = t[2 * joint + 1];
        const float v0 = v[2 * joint];
        const int xi = (int)(t0 * 14.0f);
        const int yi = (int)(t1 * 14.0f);
        const bool inb = (xi >= 0) && (xi <= COL - 1) && (yi >= 0) && (yi <= COL - 1);
        const bool vis = ((int)v0) == 1;
        const float vef = (vis && !inb) ? 0.0f : v0;
        const float veI = (((int)vef) == 1) ? 1.0f : 0.0f;
        cntf = veI;

        if (vis && inb) {
            const int b2 = joint / NJ;
            const int j2 = joint - b2 * NJ;
            const int bidx = sBidx[warp][lane];
            const size_t ob = (size_t)b2 * (3 * NJ) * NPIX;
            const float ox = outp[ob + (size_t)(NJ + j2) * NPIX + bidx];
            const float oy = outp[ob + (size_t)(2 * NJ + j2) * NPIX + bidx];
            const int yc = bidx / COL;
            const int xc = bidx - yc * COL;
            const float px = (ox + (float)xc) * (1.0f / 14.0f);
            const float py = (oy + (float)yc) * (1.0f / 14.0f);
            const float dx = (px - t0) * vef;
            const float dy = (py - t1) * vef;
            d2 = fmaf(dx, dx, dy * dy);
        }
    }
    #pragma unroll
    for (int off = 16; off; off >>= 1) {
        d2   += __shfl_xor_sync(0xffffffffu, d2, off);
        cntf += __shfl_xor_sync(0xffffffffu, cntf, off);
    }

    if (lane == 0) { sred[warp][0] = d1; sred[warp][1] = d2; sred[warp][2] = cntf; }
    __syncthreads();

    if (tid == 0) {
        float a = 0.0f, bsum = 0.0f, c = 0.0f;
        #pragma unroll
        for (int w = 0; w < NWARPS; ++w) { a += sred[w][0]; bsum += sred[w][1]; c += sred[w][2]; }
        g_d1[blockIdx.x] = a;
        g_d2[blockIdx.x] = bsum;
        g_cnt[blockIdx.x] = c;
        __threadfence();
        unsigned old = atomicAdd(&g_ticket, 1u);
        s_last = (old == GRID - 1);
    }
    __syncthreads();

    // ---- last block: grid reduction ----
    if (s_last) {
        if (tid == 0) g_ticket = 0;          // net-zero per run
        __threadfence();
        double a = 0.0, bsum = 0.0, c = 0.0;
        for (int i = tid; i < GRID; i += THREADS) {
            a    += (double)g_d1[i];
            bsum += (double)g_d2[i];
            c    += (double)g_cnt[i];
        }
        #pragma unroll
        for (int off = 16; off; off >>= 1) {
            a    += __shfl_xor_sync(0xffffffffu, a, off);
            bsum += __shfl_xor_sync(0xffffffffu, bsum, off);
            c    += __shfl_xor_sync(0xffffffffu, c, off);
        }
        if (lane == 0) { dra[warp] = a; drb[warp] = bsum; drc[warp] = c; }
        __syncthreads();
        if (tid == 0) {
            double A = 0.0, B = 0.0, C = 0.0;
            #pragma unroll
            for (int w = 0; w < NWARPS; ++w) { A += dra[w]; B += drb[w]; C += drc[w]; }
            o[0] = (float)(A / C + B / C);   // n2 == cnt (v is a tiled 0/1 mask)
        }
    }
}

extern "C" void kernel_launch(void* const* d_in, const int* in_sizes, int n_in,
                              void* d_out, int out_size)
{
    const float* outp = (const float*)d_in[0];
    const float* t    = (const float*)d_in[1];
    const float* v    = (const float*)d_in[2];

    GParams gp;
    {
        double w[9], ws = 0.0;
        for (int k = 0; k < 9; ++k) { w[k] = exp(-0.5 * (double)((k - 4) * (k - 4))); ws += w[k]; }
        for (int k = 0; k < 9; ++k) w[k] /= ws;
        for (int r = 0; r < COL; ++r)
            for (int c = 0; c < COL; ++c) {
                double s = 0.0;
                for (int k = 0; k < 9; ++k) {
                    int rr = r + k;   // padded row, pad=4, 'symmetric'
                    int m = (rr < 4) ? (3 - rr) : ((rr > 17) ? (31 - rr) : (rr - 4));
                    if (m == c) s += w[k];
                }
                gp.GT[c * COL + r] = (float)s;
            }
        for (int c = 0; c < COL; ++c) {
            float mn = 1e30f, mx = -1e30f;
            for (int r = 0; r < COL; ++r) {
                float gv = gp.GT[c * COL + r];
                mn = fminf(mn, gv);
                mx = fmaxf(mx, gv);
            }
            gp.cmin[c] = mn;
            gp.cmax[c] = mx;
        }
        for (int yic = 0; yic < COL; ++yic)
            for (int xic = 0; xic < COL; ++xic) {
                float mn = gp.cmin[yic] * gp.cmin[xic];
                float mx = gp.cmax[yic] * gp.cmax[xic];
                float inv = 1.0f / (mx - mn);
                double s = 0.0;
                for (int y = 0; y < COL; ++y)
                    for (int x = 0; x < COL; ++x) {
                        float tt = gp.GT[yic * COL + y] * gp.GT[xic * COL + x];
                        float ttn = (tt - mn) * inv;
                        s += (double)ttn * (double)ttn;
                    }
                gp.T2[yic * COL + xic] = (float)s;
            }
    }

    main_kernel<<<GRID, THREADS>>>(outp, t, v, (float*)d_out, gp);
}

// round 13
// speedup vs baseline: 1.6511x; 1.0458x over previous
#include <cuda_runtime.h>
#include <math.h>

#define COL 14
#define NJ 14
#define NPIX 196
#define NB 8192
#define NJOINT (NB * NJ)                   // 114688
#define THREADS 256
#define NWARPS 8
#define GRID 608                           // ~152 SMs x 4-5 CTAs: single wave
#define WTOT (GRID * NWARPS)               // 4864 warps
#define NTASKS (NJOINT / 8)                // 14336 tasks of 8 joints
#define SLOTS 3

struct GParams {
    float GT[NPIX];      // GT[c*14+r] = G[r][c]
    float T2[NPIX];      // sum ttn^2 per (yi,xi)
    float m2invT[NPIX];  // -2 * 1/(mx-mn) per (yi,xi)
    float m2nmiT[NPIX];  // -2 * (-mn/(mx-mn)) per (yi,xi)
};

__device__ float    g_d1[GRID];
__device__ float    g_d2[GRID];
__device__ float    g_cnt[GRID];
__device__ unsigned g_ticket;   // zero-init at load; net-zero per run

// ---- packed f32x2 helpers ----
__device__ __forceinline__ unsigned long long pack2(float lo, float hi) {
    unsigned long long r;
    asm("mov.b64 %0,{%1,%2};" : "=l"(r) : "f"(lo), "f"(hi));
    return r;
}
__device__ __forceinline__ void unpack2(unsigned long long p, float& lo, float& hi) {
    asm("mov.b64 {%0,%1},%2;" : "=f"(lo), "=f"(hi) : "l"(p));
}
__device__ __forceinline__ unsigned long long mul2(unsigned long long a, unsigned long long b) {
    unsigned long long r;
    asm("mul.rn.f32x2 %0,%1,%2;" : "=l"(r) : "l"(a), "l"(b));
    return r;
}
__device__ __forceinline__ unsigned long long add2(unsigned long long a, unsigned long long b) {
    unsigned long long r;
    asm("add.rn.f32x2 %0,%1,%2;" : "=l"(r) : "l"(a), "l"(b));
    return r;
}
__device__ __forceinline__ unsigned long long fma2(unsigned long long a, unsigned long long b,
                                                   unsigned long long c) {
    unsigned long long r;
    asm("fma.rn.f32x2 %0,%1,%2,%3;" : "=l"(r) : "l"(a), "l"(b), "l"(c));
    return r;
}

#define CP_ASYNC16(dst_u32, src_ptr) \
    asm volatile("cp.async.cg.shared.global [%0], [%1], 16;" \
                 :: "r"(dst_u32), "l"(src_ptr) : "memory")
#define CP_COMMIT() asm volatile("cp.async.commit_group;" ::: "memory")
#define CP_WAIT(n)  asm volatile("cp.async.wait_group %0;" :: "n"(n) : "memory")

__global__ __launch_bounds__(THREADS, 5) void main_kernel(
    const float* __restrict__ outp,
    const float* __restrict__ t,
    const float* __restrict__ v,
    float* __restrict__ o,
    const GParams gp)
{
    __shared__ __align__(16) float sH[NWARPS * SLOTS * 2 * NPIX];   // 37632 B
    __shared__ __align__(16) float sGT[NPIX];
    __shared__ float sred[NWARPS][3];
    __shared__ int   sBidx[NWARPS][32];
    __shared__ int   s_last;
    __shared__ double dra[NWARPS], drb[NWARPS], drc[NWARPS];

    const int tid = threadIdx.x;
    if (tid < NPIX) sGT[tid] = gp.GT[tid];
    __syncthreads();

    const int lane = tid & 31;
    const int warp = tid >> 5;
    const int gwarp = blockIdx.x * NWARPS + warp;
    const bool hasB = lane < 17;
    const int base4 = 4 * lane;
    const int baseByte = 16 * lane;

    const int ntask = (gwarp < NTASKS - 2 * WTOT) ? 3 : 2;
    const int ng = 4 * ntask;            // groups of 2 joints

    const unsigned sHbase =
        (unsigned)__cvta_generic_to_shared(&sH[warp * (SLOTS * 2 * NPIX)]);
    const float* sHw = &sH[warp * (SLOTS * 2 * NPIX)];

    // ---- per-lane pair geometry ----
    int ybO[4], xbO[4];
    {
        #pragma unroll
        for (int p = 0; p < 4; ++p) {
            int e0 = (p < 2) ? (base4 + 2 * p) : (128 + base4 + 2 * (p - 2));
            if (p >= 2 && !hasB) e0 = 0;
            int y = e0 / COL;
            ybO[p] = y * 4;
            xbO[p] = (e0 - y * COL) * 4;
        }
    }

    auto group_joint0 = [&](int gg) {
        const int task = gg >> 2;
        return (gwarp + task * WTOT) * 8 + (gg & 3) * 2;
    };

    auto issue = [&](int gg, int slot) {
        const int j0 = group_joint0(gg);
        #pragma unroll
        for (int i = 0; i < 2; ++i) {
            const int joint = j0 + i;
            const int b2 = joint / NJ;
            const int j2 = joint - b2 * NJ;
            const char* hb = reinterpret_cast<const char*>(
                outp + ((size_t)b2 * (3 * NJ) + j2) * NPIX);
            const unsigned dst = sHbase + (slot * 2 + i) * (NPIX * 4);
            CP_ASYNC16(dst + baseByte, hb + baseByte);
            if (hasB) CP_ASYNC16(dst + 512 + baseByte, hb + 512 + baseByte);
        }
        CP_COMMIT();
    };

    float d1 = 0.0f;

    auto compute = [&](int gg, int slot) {
        const int j0 = group_joint0(gg);
        const int bslot = (gg >> 2) * 8 + (gg & 3) * 2;
        const float4 tv = *reinterpret_cast<const float4*>(t + 2 * (size_t)j0);
        const float4 vv = *reinterpret_cast<const float4*>(v + 2 * (size_t)j0);
        #pragma unroll
        for (int i = 0; i < 2; ++i) {
            const float* sj = sHw + (slot * 2 + i) * NPIX;
            const float4 a = *reinterpret_cast<const float4*>(sj + base4);
            float4 b = make_float4(0.0f, 0.0f, 0.0f, 0.0f);
            if (hasB) b = *reinterpret_cast<const float4*>(sj + 128 + base4);

            const unsigned long long p01 = pack2(a.x, a.y);
            const unsigned long long p23 = pack2(a.z, a.w);
            const unsigned long long p45 = pack2(b.x, b.y);
            const unsigned long long p67 = pack2(b.z, b.w);

            unsigned long long s2 = fma2(p01, p01, mul2(p23, p23));
            s2 = fma2(p45, p45, s2);
            s2 = fma2(p67, p67, s2);
            float h2lo, h2hi; unpack2(s2, h2lo, h2hi);
            const float ph2 = h2lo + h2hi;

            const float t0 = i ? tv.z : tv.x;
            const float t1 = i ? tv.w : tv.y;
            const float v0 = i ? vv.z : vv.x;
            const int xi = (int)(t0 * 14.0f);
            const int yi = (int)(t1 * 14.0f);
            const bool inb = (xi >= 0) && (xi <= COL - 1) && (yi >= 0) && (yi <= COL - 1);
            const bool vis = ((int)v0) == 1;
            const bool scat = vis && inb;       // warp-uniform

            if (scat) {
                unsigned long long sh = add2(add2(p01, p23), add2(p45, p67));
                float shlo, shhi; unpack2(sh, shlo, shhi);
                const float ph = shlo + shhi;

                const char* gyrowB = reinterpret_cast<const char*>(sGT + yi * COL);
                const char* gxrowB = reinterpret_cast<const char*>(sGT + xi * COL);
                unsigned long long acc = 0ull;
                {
                    const float gy = *(const float*)(gyrowB + ybO[0]);
                    const unsigned long long gx2 = *(const unsigned long long*)(gxrowB + xbO[0]);
                    acc = fma2(mul2(gx2, p01), pack2(gy, gy), acc);
                }
                {
                    const float gy = *(const float*)(gyrowB + ybO[1]);
                    const unsigned long long gx2 = *(const unsigned long long*)(gxrowB + xbO[1]);
                    acc = fma2(mul2(gx2, p23), pack2(gy, gy), acc);
                }
                {
                    const float gy = *(const float*)(gyrowB + ybO[2]);
                    const unsigned long long gx2 = *(const unsigned long long*)(gxrowB + xbO[2]);
                    acc = fma2(mul2(gx2, p45), pack2(gy, gy), acc);
                }
                {
                    const float gy = *(const float*)(gyrowB + ybO[3]);
                    const unsigned long long gx2 = *(const unsigned long long*)(gxrowB + xbO[3]);
                    acc = fma2(mul2(gx2, p67), pack2(gy, gy), acc);
                }
                float htlo, hthi; unpack2(acc, htlo, hthi);
                const float phtt = htlo + hthi;

                const int cell = yi * COL + xi;     // warp-uniform -> LDC
                const float m2inv = gp.m2invT[cell];
                const float m2nmi = gp.m2nmiT[cell];

                d1 += fmaf(m2inv, phtt, fmaf(m2nmi, ph, ph2));
                if (lane == 0) d1 += gp.T2[cell];

                float best = fmaxf(fmaxf(a.x, a.y), fmaxf(a.z, a.w));
                if (hasB) best = fmaxf(best, fmaxf(fmaxf(b.x, b.y), fmaxf(b.z, b.w)));
                int idx = 0x7fffffff;
                if (hasB) {
                    idx = (b.w == best) ? (131 + base4) : idx;
                    idx = (b.z == best) ? (130 + base4) : idx;
                    idx = (b.y == best) ? (129 + base4) : idx;
                    idx = (b.x == best) ? (128 + base4) : idx;
                }
                idx = (a.w == best) ? (3 + base4) : idx;
                idx = (a.z == best) ? (2 + base4) : idx;
                idx = (a.y == best) ? (1 + base4) : idx;
                idx = (a.x == best) ? (base4) : idx;

                unsigned u = __float_as_uint(best);
                unsigned mono = ((int)u < 0) ? ~u : (u | 0x80000000u);
                unsigned mmax = __reduce_max_sync(0xffffffffu, mono);
                int cand = (mono == mmax) ? idx : 0x7fffffff;
                int bidx = __reduce_min_sync(0xffffffffu, cand);
                if (lane == 0) sBidx[warp][bslot + i] = bidx;
            } else {
                float pr = 0.0f;
                if (lane < 4) {
                    pr = fmaf(a.x, a.x, a.y * a.y);
                    if (lane < 3) pr += fmaf(a.z, a.z, a.w * a.w);
                }
                d1 += ph2 - pr;
            }
        }
    };

    // ---- continuous 3-slot pipeline over all ng groups ----
    issue(0, 0); issue(1, 1); issue(2, 2);
    {
        int slot = 0;
        for (int gg = 0; gg + 3 < ng; ++gg) {
            CP_WAIT(2);
            compute(gg, slot);
            issue(gg + 3, slot);
            slot = (slot == 2) ? 0 : slot + 1;
        }
        CP_WAIT(2); compute(ng - 3, slot); slot = (slot == 2) ? 0 : slot + 1;
        CP_WAIT(1); compute(ng - 2, slot); slot = (slot == 2) ? 0 : slot + 1;
        CP_WAIT(0); compute(ng - 1, slot);
    }

    // warp-reduce d1
    #pragma unroll
    for (int off = 16; off; off >>= 1)
        d1 += __shfl_xor_sync(0xffffffffu, d1, off);

    __syncwarp();

    // ---- phase B: one joint per lane (up to 24) ----
    float d2 = 0.0f, cntf = 0.0f;
    if (lane < ntask * 8) {
        const int joint = (gwarp + (lane >> 3) * WTOT) * 8 + (lane & 7);
        const float t0 = t[2 * joint];
        const float t1 = t[2 * joint + 1];
        const float v0 = v[2 * joint];
        const int xi = (int)(t0 * 14.0f);
        const int yi = (int)(t1 * 14.0f);
        const bool inb = (xi >= 0) && (xi <= COL - 1) && (yi >= 0) && (yi <= COL - 1);
        const bool vis = ((int)v0) == 1;
        const float vef = (vis && !inb) ? 0.0f : v0;
        const float veI = (((int)vef) == 1) ? 1.0f : 0.0f;
        cntf = veI;

        if (vis && inb) {
            const int b2 = joint / NJ;
            const int j2 = joint - b2 * NJ;
            const int bidx = sBidx[warp][lane];
            const size_t ob = (size_t)b2 * (3 * NJ) * NPIX;
            const float ox = outp[ob + (size_t)(NJ + j2) * NPIX + bidx];
            const float oy = outp[ob + (size_t)(2 * NJ + j2) * NPIX + bidx];
            const int yc = bidx / COL;
            const int xc = bidx - yc * COL;
            const float px = (ox + (float)xc) * (1.0f / 14.0f);
            const float py = (oy + (float)yc) * (1.0f / 14.0f);
            const float dx = (px - t0) * vef;
            const float dy = (py - t1) * vef;
            d2 = fmaf(dx, dx, dy * dy);
        }
    }
    #pragma unroll
    for (int off = 16; off; off >>= 1) {
        d2   += __shfl_xor_sync(0xffffffffu, d2, off);
        cntf += __shfl_xor_sync(0xffffffffu, cntf, off);
    }

    if (lane == 0) { sred[warp][0] = d1; sred[warp][1] = d2; sred[warp][2] = cntf; }
    __syncthreads();

    if (tid == 0) {
        float a = 0.0f, bsum = 0.0f, c = 0.0f;
        #pragma unroll
        for (int w = 0; w < NWARPS; ++w) { a += sred[w][0]; bsum += sred[w][1]; c += sred[w][2]; }
        g_d1[blockIdx.x] = a;
        g_d2[blockIdx.x] = bsum;
        g_cnt[blockIdx.x] = c;
        __threadfence();
        unsigned old = atomicAdd(&g_ticket, 1u);
        s_last = (old == GRID - 1);
    }
    __syncthreads();

    // ---- last block: grid reduction ----
    if (s_last) {
        if (tid == 0) g_ticket = 0;          // net-zero per run
        __threadfence();
        double a = 0.0, bsum = 0.0, c = 0.0;
        for (int i = tid; i < GRID; i += THREADS) {
            a    += (double)g_d1[i];
            bsum += (double)g_d2[i];
            c    += (double)g_cnt[i];
        }
        #pragma unroll
        for (int off = 16; off; off >>= 1) {
            a    += __shfl_xor_sync(0xffffffffu, a, off);
            bsum += __shfl_xor_sync(0xffffffffu, bsum, off);
            c    += __shfl_xor_sync(0xffffffffu, c, off);
        }
        if (lane == 0) { dra[warp] = a; drb[warp] = bsum; drc[warp] = c; }
        __syncthreads();
        if (tid == 0) {
            double A = 0.0, B = 0.0, C = 0.0;
            #pragma unroll
            for (int w = 0; w < NWARPS; ++w) { A += dra[w]; B += drb[w]; C += drc[w]; }
            o[0] = (float)(A / C + B / C);   // n2 == cnt (v is a tiled 0/1 mask)
        }
    }
}

extern "C" void kernel_launch(void* const* d_in, const int* in_sizes, int n_in,
                              void* d_out, int out_size)
{
    const float* outp = (const float*)d_in[0];
    const float* t    = (const float*)d_in[1];
    const float* v    = (const float*)d_in[2];

    GParams gp;
    {
        double w[9], ws = 0.0;
        for (int k = 0; k < 9; ++k) { w[k] = exp(-0.5 * (double)((k - 4) * (k - 4))); ws += w[k]; }
        for (int k = 0; k < 9; ++k) w[k] /= ws;
        for (int r = 0; r < COL; ++r)
            for (int c = 0; c < COL; ++c) {
                double s = 0.0;
                for (int k = 0; k < 9; ++k) {
                    int rr = r + k;   // padded row, pad=4, 'symmetric'
                    int m = (rr < 4) ? (3 - rr) : ((rr > 17) ? (31 - rr) : (rr - 4));
                    if (m == c) s += w[k];
                }
                gp.GT[c * COL + r] = (float)s;
            }
        float cmin[COL], cmax[COL];
        for (int c = 0; c < COL; ++c) {
            float mn = 1e30f, mx = -1e30f;
            for (int r = 0; r < COL; ++r) {
                float gv = gp.GT[c * COL + r];
                mn = fminf(mn, gv);
                mx = fmaxf(mx, gv);
            }
            cmin[c] = mn;
            cmax[c] = mx;
        }
        for (int yic = 0; yic < COL; ++yic)
            for (int xic = 0; xic < COL; ++xic) {
                float mn = cmin[yic] * cmin[xic];
                float mx = cmax[yic] * cmax[xic];
                double invd = 1.0 / ((double)mx - (double)mn);
                float inv = (float)invd;
                double s = 0.0;
                for (int y = 0; y < COL; ++y)
                    for (int x = 0; x < COL; ++x) {
                        float tt = gp.GT[yic * COL + y] * gp.GT[xic * COL + x];
                        float ttn = (tt - mn) * inv;
                        s += (double)ttn * (double)ttn;
                    }
                const int cell = yic * COL + xic;
                gp.T2[cell] = (float)s;
                gp.m2invT[cell] = -2.0f * inv;
                gp.m2nmiT[cell] = -2.0f * (-mn * inv);
            }
    }

    main_kernel<<<GRID, THREADS>>>(outp, t, v, (float*)d_out, gp);
}